// round 14
// baseline (speedup 1.0000x reference)
#include <cuda_runtime.h>
#include <cuda_fp16.h>
#include <cstdint>
#include <math.h>

// Problem constants
#define BSZ   32768
#define HDIM  512
#define KTOT  1024          // concat(x,h)
#define NPK   2048          // 4 gates * 512, interleaved (j,gate): col = 4*j+g

// GEMM tiling (warp-level mma.sync path; base-PTX features only)
#define BM    128           // rows per CTA
#define BN    128           // packed cols per CTA (= 32 j's)
#define BK    64            // K per iteration
#define NCH   (KTOT / BK)   // 16 iterations
#define NST   3             // cp.async pipeline stages

// A and B both single fp16 (error budget measured: ~2.1e-4 total, gate 1e-3).
__device__ __half g_Apk[(size_t)BSZ * KTOT];   // 64 MB
__device__ __half g_Bpk[(size_t)NPK * KTOT];   // 4 MB
__device__ float  g_bp[NPK];

// ---------------------------------------------------------------- helpers
__device__ __forceinline__ uint32_t smem_u32(const void* p) {
    uint32_t a;
    asm("{ .reg .u64 t; cvta.to.shared.u64 t, %1; cvt.u32.u64 %0, t; }" : "=r"(a) : "l"(p));
    return a;
}
__device__ __forceinline__ uint32_t swz(uint32_t off) {   // xor swizzle on 128B rows
    return off ^ ((off >> 3) & 0x70);
}
__device__ __forceinline__ void cpa16(uint32_t dst, const void* src) {
    asm volatile("cp.async.cg.shared.global [%0], [%1], 16;" :: "r"(dst), "l"(src) : "memory");
}
__device__ __forceinline__ void cpa_commit() { asm volatile("cp.async.commit_group;" ::: "memory"); }
__device__ __forceinline__ void cpa_wait1()  { asm volatile("cp.async.wait_group 1;" ::: "memory"); }
__device__ __forceinline__ void cpa_wait0()  { asm volatile("cp.async.wait_group 0;" ::: "memory"); }

__device__ __forceinline__ void ldsm4(uint32_t* r, uint32_t addr) {
    asm volatile("ldmatrix.sync.aligned.m8n8.x4.shared.b16 {%0,%1,%2,%3}, [%4];"
        : "=r"(r[0]), "=r"(r[1]), "=r"(r[2]), "=r"(r[3]) : "r"(addr));
}
__device__ __forceinline__ void mma16816(float* d, const uint32_t* a, const uint32_t* b) {
    asm volatile(
        "mma.sync.aligned.m16n8k16.row.col.f32.f16.f16.f32 "
        "{%0,%1,%2,%3}, {%4,%5,%6,%7}, {%8,%9}, {%0,%1,%2,%3};"
        : "+f"(d[0]), "+f"(d[1]), "+f"(d[2]), "+f"(d[3])
        : "r"(a[0]), "r"(a[1]), "r"(a[2]), "r"(a[3]), "r"(b[0]), "r"(b[1]));
}

// ---------------------------------------------------------------- pre-passes
__global__ void conv_A(const float* __restrict__ x, const float* __restrict__ h) {
    size_t t = (size_t)blockIdx.x * blockDim.x + threadIdx.x;
    if (t >= (size_t)BSZ * (KTOT / 8)) return;
    int row = (int)(t >> 7);            // 128 groups of 8 per row
    int kg  = ((int)t & 127) * 8;
    const float* src = (kg < HDIM) ? (x + (size_t)row * HDIM + kg)
                                   : (h + (size_t)row * HDIM + (kg - HDIM));
    float4 v0 = *(const float4*)(src);
    float4 v1 = *(const float4*)(src + 4);
    float v[8] = {v0.x, v0.y, v0.z, v0.w, v1.x, v1.y, v1.z, v1.w};
    __half o[8];
    #pragma unroll
    for (int e = 0; e < 8; e++) o[e] = __float2half(v[e]);
    *(uint4*)&g_Apk[(size_t)row * KTOT + kg] = *(uint4*)o;
}

__global__ void pack_W(
    const float* __restrict__ Uf, const float* __restrict__ Vf, const float* __restrict__ bf,
    const float* __restrict__ Ui, const float* __restrict__ Vi, const float* __restrict__ bi,
    const float* __restrict__ Uo, const float* __restrict__ Vo, const float* __restrict__ bo,
    const float* __restrict__ Uc, const float* __restrict__ Vc, const float* __restrict__ bc)
{
    int idx = blockIdx.x * blockDim.x + threadIdx.x;   // over KTOT*HDIM
    if (idx >= KTOT * HDIM) return;
    int j = idx & (HDIM - 1);
    int k = idx >> 9;
    const float* Us[4] = {Uf, Ui, Uo, Uc};
    const float* Vs[4] = {Vf, Vi, Vo, Vc};
    const float* bs[4] = {bf, bi, bo, bc};
    #pragma unroll
    for (int g = 0; g < 4; g++) {
        float v = (k < HDIM) ? Us[g][(size_t)k * HDIM + j]
                             : Vs[g][(size_t)(k - HDIM) * HDIM + j];
        size_t n = (size_t)(4 * j + g);
        g_Bpk[n * KTOT + k] = __float2half(v);
        if (k == 0) g_bp[4 * j + g] = bs[g][j];
    }
}

// ---------------------------------------------------------------- main GEMM
// Stage (32KB): A 16KB | B 16KB. Each: 128 rows x 128B (64 fp16),
// xor-swizzled within the 128B row.
#define STAGE_BYTES 32768
#define SMEM_TOTAL  (NST * STAGE_BYTES)

__device__ __forceinline__ void load_chunk(uint32_t st,
                                           const __half* Asrc,
                                           const __half* Bsrc,
                                           int c, int tid)
{
    const char* ap = (const char*)Asrc;
    const char* bp = (const char*)Bsrc;
    #pragma unroll
    for (int kq = 0; kq < 4; kq++) {
        int q = tid + 256 * kq;            // 0..1023 16B-units per sub-tile
        int r = q >> 3, u = q & 7;
        uint32_t soff = swz((uint32_t)(r << 7) + (uint32_t)(u << 4));
        size_t go = ((size_t)r << 11) + ((size_t)c << 7) + ((size_t)u << 4);
        cpa16(st + soff, ap + go);
        cpa16(st + 16384 + soff, bp + go);
    }
}

__global__ void __launch_bounds__(256, 1) lstm_gemm(
    const float* __restrict__ c_in,
    float* __restrict__ out_h, float* __restrict__ out_c)
{
    extern __shared__ char smem[];
    uint32_t sb = smem_u32(smem);
    const int tid  = threadIdx.x;
    const int lane = tid & 31;
    const int wid  = tid >> 5;
    const int wm   = wid & 1;      // 2 warp-rows of 64
    const int wn   = wid >> 1;     // 4 warp-cols of 32
    const int brow = blockIdx.y * BM;
    const int bcol = blockIdx.x * BN;

    const __half* Asrc = g_Apk + (size_t)brow * KTOT;
    const __half* Bsrc = g_Bpk + (size_t)bcol * KTOT;

    float acc[4][4][4];
    #pragma unroll
    for (int mt = 0; mt < 4; mt++)
        #pragma unroll
        for (int nt = 0; nt < 4; nt++)
            #pragma unroll
            for (int e = 0; e < 4; e++) acc[mt][nt][e] = 0.f;

    // prologue: fill 2 stages
    load_chunk(sb + 0 * STAGE_BYTES, Asrc, Bsrc, 0, tid); cpa_commit();
    load_chunk(sb + 1 * STAGE_BYTES, Asrc, Bsrc, 1, tid); cpa_commit();

    // ldmatrix address components
    const int a_row = wm * 64 + (lane & 15);              // + mt*16
    const int a_kb  = (lane >> 4) * 16;                   // + g*32
    const int b_row = (lane & 7) + ((lane >> 4) & 1) * 8; // + wn*32 + ntp*16
    const int b_kb  = ((lane >> 3) & 1) * 16;             // + g*32

    for (int i = 0; i < NCH; i++) {
        if (i == NCH - 1) cpa_wait0(); else cpa_wait1();
        __syncthreads();

        if (i + 2 < NCH) {
            load_chunk(sb + ((i + 2) % 3) * STAGE_BYTES, Asrc, Bsrc, i + 2, tid);
            cpa_commit();
        }

        uint32_t st = sb + (i % 3) * STAGE_BYTES;

        #pragma unroll
        for (int g = 0; g < 4; g++) {                     // 4 k16 groups in BK=64
            uint32_t kk = (uint32_t)(g * 32);
            uint32_t ah[4][4], bh[4][2];
            #pragma unroll
            for (int mt = 0; mt < 4; mt++) {
                uint32_t roff = (uint32_t)((a_row + mt * 16) << 7);
                ldsm4(ah[mt], st + swz(roff + (uint32_t)a_kb + kk));
            }
            #pragma unroll
            for (int ntp = 0; ntp < 2; ntp++) {
                uint32_t roff = (uint32_t)((wn * 32 + ntp * 16 + b_row) << 7);
                uint32_t t4[4];
                ldsm4(t4, st + 16384 + swz(roff + (uint32_t)b_kb + kk));
                bh[2 * ntp][0] = t4[0]; bh[2 * ntp][1] = t4[1];
                bh[2 * ntp + 1][0] = t4[2]; bh[2 * ntp + 1][1] = t4[3];
            }
            #pragma unroll
            for (int mt = 0; mt < 4; mt++)
                #pragma unroll
                for (int nt = 0; nt < 4; nt++)
                    mma16816(acc[mt][nt], ah[mt], bh[nt]);
        }
    }

    // -------- epilogue: gates in registers, h/c staged via SMEM (coalesced)
    __syncthreads();
    float* shC = (float*)smem;            // [128][33]
    float* shH = shC + 128 * 33;          // [128][33]
    const int j0 = bcol >> 2;             // 32 j's per CTA

    for (int idx = tid; idx < 128 * 32; idx += 256) {
        int r = idx >> 5, j = idx & 31;
        shC[r * 33 + j] = c_in[(size_t)(brow + r) * HDIM + j0 + j];
    }
    __syncthreads();

    #pragma unroll
    for (int mt = 0; mt < 4; mt++) {
        #pragma unroll
        for (int nt = 0; nt < 4; nt++) {
            int nb = wn * 32 + nt * 8 + 2 * (lane & 3);   // local packed col (pair base)
            float bA = __ldg(&g_bp[bcol + nb]);
            float bB = __ldg(&g_bp[bcol + nb + 1]);
            #pragma unroll
            for (int hf = 0; hf < 2; hf++) {
                int row = wm * 64 + mt * 16 + (lane >> 2) + hf * 8;
                float p0 = acc[mt][nt][2 * hf + 0] + bA;
                float p1 = acc[mt][nt][2 * hf + 1] + bB;
                float q0 = __shfl_xor_sync(0xffffffffu, p0, 1);
                float q1 = __shfl_xor_sync(0xffffffffu, p1, 1);
                if ((lane & 1) == 0) {
                    // even lane holds (f,i); partner lane holds (o,c)
                    float fg = 1.f / (1.f + __expf(-p0));
                    float ig = 1.f / (1.f + __expf(-p1));
                    float og = 1.f / (1.f + __expf(-q0));
                    float ch = tanhf(q1);
                    int jl = nb >> 2;
                    float co = shC[row * 33 + jl];
                    float cn = fg * co + ig * ch;
                    float hn = og * tanhf(cn);
                    shC[row * 33 + jl] = cn;
                    shH[row * 33 + jl] = hn;
                }
            }
        }
    }
    __syncthreads();

    for (int idx = tid; idx < 128 * 32; idx += 256) {
        int r = idx >> 5, j = idx & 31;
        size_t go = (size_t)(brow + r) * HDIM + j0 + j;
        out_h[go] = shH[r * 33 + j];
        out_c[go] = shC[r * 33 + j];
    }
}

// ---------------------------------------------------------------- head
__global__ void head_kernel(const float* __restrict__ hbuf,
                            const float* __restrict__ Wout,
                            const float* __restrict__ bout,
                            float* __restrict__ pre_label)
{
    int warp = (blockIdx.x * blockDim.x + threadIdx.x) >> 5;
    int lane = threadIdx.x & 31;
    if (warp >= BSZ) return;
    const float* row = hbuf + (size_t)warp * HDIM;
    float s0 = 0.f, s1 = 0.f;
    #pragma unroll 4
    for (int j = lane; j < HDIM; j += 32) {
        float v = row[j];
        s0 += v * Wout[j * 2 + 0];
        s1 += v * Wout[j * 2 + 1];
    }
    #pragma unroll
    for (int off = 16; off; off >>= 1) {
        s0 += __shfl_xor_sync(0xffffffffu, s0, off);
        s1 += __shfl_xor_sync(0xffffffffu, s1, off);
    }
    if (lane == 0) {
        s0 += bout[0];
        s1 += bout[1];
        float mx = fmaxf(s0, s1);
        float e0 = __expf(s0 - mx), e1 = __expf(s1 - mx);
        float inv = 1.f / (e0 + e1);
        pre_label[warp * 2 + 0] = e0 * inv;
        pre_label[warp * 2 + 1] = e1 * inv;
    }
}

// ---------------------------------------------------------------- launch
extern "C" void kernel_launch(void* const* d_in, const int* in_sizes, int n_in,
                              void* d_out, int out_size)
{
    const float* x    = (const float*)d_in[0];
    const float* h    = (const float*)d_in[1];
    const float* c    = (const float*)d_in[2];
    const float* Uf   = (const float*)d_in[3];
    const float* Vf   = (const float*)d_in[4];
    const float* bf   = (const float*)d_in[5];
    const float* Ui   = (const float*)d_in[6];
    const float* Vi   = (const float*)d_in[7];
    const float* bi   = (const float*)d_in[8];
    const float* Uo   = (const float*)d_in[9];
    const float* Vo   = (const float*)d_in[10];
    const float* bo   = (const float*)d_in[11];
    const float* Uc   = (const float*)d_in[12];
    const float* Vc   = (const float*)d_in[13];
    const float* bc   = (const float*)d_in[14];
    const float* Wout = (const float*)d_in[15];
    const float* bout = (const float*)d_in[16];

    float* out       = (float*)d_out;
    float* pre_label = out;                       // [B,2]
    float* out_h     = out + (size_t)BSZ * 2;     // [B,512]
    float* out_c     = out_h + (size_t)BSZ * HDIM;

    cudaFuncSetAttribute(lstm_gemm, cudaFuncAttributeMaxDynamicSharedMemorySize, SMEM_TOTAL);

    pack_W<<<(KTOT * HDIM + 255) / 256, 256>>>(Uf, Vf, bf, Ui, Vi, bi,
                                               Uo, Vo, bo, Uc, Vc, bc);
    conv_A<<<(int)(((size_t)BSZ * (KTOT / 8) + 255) / 256), 256>>>(x, h);
    lstm_gemm<<<dim3(NPK / BN, BSZ / BM), 256, SMEM_TOTAL>>>(c, out_h, out_c);
    head_kernel<<<(BSZ * 32 + 255) / 256, 256>>>(out_h, Wout, bout, pre_label);
}

// round 16
// speedup vs baseline: 2.0460x; 2.0460x over previous
#include <cuda_runtime.h>
#include <cuda_fp16.h>
#include <cstdint>
#include <math.h>

// Problem constants
#define BSZ   32768
#define HDIM  512
#define KTOT  1024          // concat(x,h)
#define NPK   2048          // 4 gates * 512, interleaved (j,gate): col = 4*j+g

// GEMM tiling: 512 threads, 16 warps (4 per SMSP), warp tile 64x32
#define BM    256           // rows per CTA
#define BN    128           // packed cols per CTA (= 32 j's)
#define BK    64            // K per iteration
#define NCH   (KTOT / BK)   // 16 iterations
#define NST   3             // cp.async pipeline stages
#define NTHR  512

// A and B single fp16 (measured error 2.2e-4, gate 1e-3).
__device__ __half g_Apk[(size_t)BSZ * KTOT];   // 64 MB
__device__ __half g_Bpk[(size_t)NPK * KTOT];   // 4 MB
__device__ float  g_bp[NPK];

// ---------------------------------------------------------------- helpers
__device__ __forceinline__ uint32_t smem_u32(const void* p) {
    uint32_t a;
    asm("{ .reg .u64 t; cvta.to.shared.u64 t, %1; cvt.u32.u64 %0, t; }" : "=r"(a) : "l"(p));
    return a;
}
__device__ __forceinline__ uint32_t swz(uint32_t off) {   // xor swizzle on 128B rows
    return off ^ ((off >> 3) & 0x70);
}
__device__ __forceinline__ void cpa16(uint32_t dst, const void* src) {
    asm volatile("cp.async.cg.shared.global [%0], [%1], 16;" :: "r"(dst), "l"(src) : "memory");
}
__device__ __forceinline__ void cpa_commit() { asm volatile("cp.async.commit_group;" ::: "memory"); }
__device__ __forceinline__ void cpa_wait1()  { asm volatile("cp.async.wait_group 1;" ::: "memory"); }
__device__ __forceinline__ void cpa_wait0()  { asm volatile("cp.async.wait_group 0;" ::: "memory"); }

__device__ __forceinline__ void ldsm4(uint32_t* r, uint32_t addr) {
    asm volatile("ldmatrix.sync.aligned.m8n8.x4.shared.b16 {%0,%1,%2,%3}, [%4];"
        : "=r"(r[0]), "=r"(r[1]), "=r"(r[2]), "=r"(r[3]) : "r"(addr));
}
__device__ __forceinline__ void mma16816(float* d, const uint32_t* a, const uint32_t* b) {
    asm volatile(
        "mma.sync.aligned.m16n8k16.row.col.f32.f16.f16.f32 "
        "{%0,%1,%2,%3}, {%4,%5,%6,%7}, {%8,%9}, {%0,%1,%2,%3};"
        : "+f"(d[0]), "+f"(d[1]), "+f"(d[2]), "+f"(d[3])
        : "r"(a[0]), "r"(a[1]), "r"(a[2]), "r"(a[3]), "r"(b[0]), "r"(b[1]));
}

// ---------------------------------------------------------------- pre-passes
__global__ void conv_A(const float* __restrict__ x, const float* __restrict__ h) {
    size_t t = (size_t)blockIdx.x * blockDim.x + threadIdx.x;
    if (t >= (size_t)BSZ * (KTOT / 8)) return;
    int row = (int)(t >> 7);            // 128 groups of 8 per row
    int kg  = ((int)t & 127) * 8;
    const float* src = (kg < HDIM) ? (x + (size_t)row * HDIM + kg)
                                   : (h + (size_t)row * HDIM + (kg - HDIM));
    float4 v0 = *(const float4*)(src);
    float4 v1 = *(const float4*)(src + 4);
    float v[8] = {v0.x, v0.y, v0.z, v0.w, v1.x, v1.y, v1.z, v1.w};
    __half o[8];
    #pragma unroll
    for (int e = 0; e < 8; e++) o[e] = __float2half(v[e]);
    *(uint4*)&g_Apk[(size_t)row * KTOT + kg] = *(uint4*)o;
}

__global__ void pack_W(
    const float* __restrict__ Uf, const float* __restrict__ Vf, const float* __restrict__ bf,
    const float* __restrict__ Ui, const float* __restrict__ Vi, const float* __restrict__ bi,
    const float* __restrict__ Uo, const float* __restrict__ Vo, const float* __restrict__ bo,
    const float* __restrict__ Uc, const float* __restrict__ Vc, const float* __restrict__ bc)
{
    int idx = blockIdx.x * blockDim.x + threadIdx.x;   // over KTOT*HDIM
    if (idx >= KTOT * HDIM) return;
    int j = idx & (HDIM - 1);
    int k = idx >> 9;
    const float* Us[4] = {Uf, Ui, Uo, Uc};
    const float* Vs[4] = {Vf, Vi, Vo, Vc};
    const float* bs[4] = {bf, bi, bo, bc};
    #pragma unroll
    for (int g = 0; g < 4; g++) {
        float v = (k < HDIM) ? Us[g][(size_t)k * HDIM + j]
                             : Vs[g][(size_t)(k - HDIM) * HDIM + j];
        size_t n = (size_t)(4 * j + g);
        g_Bpk[n * KTOT + k] = __float2half(v);
        if (k == 0) g_bp[4 * j + g] = bs[g][j];
    }
}

// ---------------------------------------------------------------- main GEMM
// Stage (48KB): A 32KB (256 rows x 128B) | B 16KB (128 rows x 128B),
// xor-swizzled within each 128B row.
#define STAGE_BYTES 49152
#define SMEM_TOTAL  (NST * STAGE_BYTES)

__device__ __forceinline__ void load_chunk(uint32_t st,
                                           const __half* Asrc,
                                           const __half* Bsrc,
                                           int c, int tid)
{
    const char* ap = (const char*)Asrc;
    const char* bp = (const char*)Bsrc;
    #pragma unroll
    for (int kq = 0; kq < 4; kq++) {       // A: 2048 16B-units
        int q = tid + NTHR * kq;
        int r = q >> 3, u = q & 7;
        uint32_t soff = swz((uint32_t)(r << 7) + (uint32_t)(u << 4));
        size_t go = ((size_t)r << 11) + ((size_t)c << 7) + ((size_t)u << 4);
        cpa16(st + soff, ap + go);
    }
    #pragma unroll
    for (int kq = 0; kq < 2; kq++) {       // B: 1024 16B-units
        int q = tid + NTHR * kq;
        int r = q >> 3, u = q & 7;
        uint32_t soff = swz((uint32_t)(r << 7) + (uint32_t)(u << 4));
        size_t go = ((size_t)r << 11) + ((size_t)c << 7) + ((size_t)u << 4);
        cpa16(st + 32768 + soff, bp + go);
    }
}

__global__ void __launch_bounds__(NTHR, 1) lstm_gemm(
    const float* __restrict__ c_in,
    float* __restrict__ out_h, float* __restrict__ out_c)
{
    extern __shared__ char smem[];
    uint32_t sb = smem_u32(smem);
    const int tid  = threadIdx.x;
    const int lane = tid & 31;
    const int wid  = tid >> 5;
    const int wm   = wid & 3;      // 4 warp-rows of 64
    const int wn   = wid >> 2;     // 4 warp-cols of 32
    const int brow = blockIdx.y * BM;
    const int bcol = blockIdx.x * BN;

    const __half* Asrc = g_Apk + (size_t)brow * KTOT;
    const __half* Bsrc = g_Bpk + (size_t)bcol * KTOT;

    float acc[4][4][4];
    #pragma unroll
    for (int mt = 0; mt < 4; mt++)
        #pragma unroll
        for (int nt = 0; nt < 4; nt++)
            #pragma unroll
            for (int e = 0; e < 4; e++) acc[mt][nt][e] = 0.f;

    // prologue: fill 2 stages
    load_chunk(sb + 0 * STAGE_BYTES, Asrc, Bsrc, 0, tid); cpa_commit();
    load_chunk(sb + 1 * STAGE_BYTES, Asrc, Bsrc, 1, tid); cpa_commit();

    // ldmatrix address components
    const int a_row = wm * 64 + (lane & 15);              // + mt*16
    const int a_kb  = (lane >> 4) * 16;                   // + g*32
    const int b_row = (lane & 7) + ((lane >> 4) & 1) * 8; // + wn*32 + ntp*16
    const int b_kb  = ((lane >> 3) & 1) * 16;             // + g*32

    for (int i = 0; i < NCH; i++) {
        if (i == NCH - 1) cpa_wait0(); else cpa_wait1();
        __syncthreads();

        if (i + 2 < NCH) {
            load_chunk(sb + ((i + 2) % 3) * STAGE_BYTES, Asrc, Bsrc, i + 2, tid);
            cpa_commit();
        }

        uint32_t st = sb + (i % 3) * STAGE_BYTES;

        #pragma unroll
        for (int g = 0; g < 4; g++) {                     // 4 k16 groups in BK=64
            uint32_t kk = (uint32_t)(g * 32);
            uint32_t ah[4][4], bh[4][2];
            #pragma unroll
            for (int mt = 0; mt < 4; mt++) {
                uint32_t roff = (uint32_t)((a_row + mt * 16) << 7);
                ldsm4(ah[mt], st + swz(roff + (uint32_t)a_kb + kk));
            }
            #pragma unroll
            for (int ntp = 0; ntp < 2; ntp++) {
                uint32_t roff = (uint32_t)((wn * 32 + ntp * 16 + b_row) << 7);
                uint32_t t4[4];
                ldsm4(t4, st + 32768 + swz(roff + (uint32_t)b_kb + kk));
                bh[2 * ntp][0] = t4[0]; bh[2 * ntp][1] = t4[1];
                bh[2 * ntp + 1][0] = t4[2]; bh[2 * ntp + 1][1] = t4[3];
            }
            #pragma unroll
            for (int mt = 0; mt < 4; mt++)
                #pragma unroll
                for (int nt = 0; nt < 4; nt++)
                    mma16816(acc[mt][nt], ah[mt], bh[nt]);
        }
    }

    // -------- epilogue: gates in registers, h/c staged via SMEM (coalesced)
    __syncthreads();
    float* shC = (float*)smem;            // [256][33]
    float* shH = shC + 256 * 33;          // [256][33]
    const int j0 = bcol >> 2;             // 32 j's per CTA

    for (int idx = tid; idx < 256 * 32; idx += NTHR) {
        int r = idx >> 5, j = idx & 31;
        shC[r * 33 + j] = c_in[(size_t)(brow + r) * HDIM + j0 + j];
    }
    __syncthreads();

    #pragma unroll
    for (int mt = 0; mt < 4; mt++) {
        #pragma unroll
        for (int nt = 0; nt < 4; nt++) {
            int nb = wn * 32 + nt * 8 + 2 * (lane & 3);   // local packed col (pair base)
            float bA = __ldg(&g_bp[bcol + nb]);
            float bB = __ldg(&g_bp[bcol + nb + 1]);
            #pragma unroll
            for (int hf = 0; hf < 2; hf++) {
                int row = wm * 64 + mt * 16 + (lane >> 2) + hf * 8;
                float p0 = acc[mt][nt][2 * hf + 0] + bA;
                float p1 = acc[mt][nt][2 * hf + 1] + bB;
                float q0 = __shfl_xor_sync(0xffffffffu, p0, 1);
                float q1 = __shfl_xor_sync(0xffffffffu, p1, 1);
                if ((lane & 1) == 0) {
                    // even lane holds (f,i); partner lane holds (o,c)
                    float fg = 1.f / (1.f + __expf(-p0));
                    float ig = 1.f / (1.f + __expf(-p1));
                    float og = 1.f / (1.f + __expf(-q0));
                    float ch = tanhf(q1);
                    int jl = nb >> 2;
                    float co = shC[row * 33 + jl];
                    float cn = fg * co + ig * ch;
                    float hn = og * tanhf(cn);
                    shC[row * 33 + jl] = cn;
                    shH[row * 33 + jl] = hn;
                }
            }
        }
    }
    __syncthreads();

    for (int idx = tid; idx < 256 * 32; idx += NTHR) {
        int r = idx >> 5, j = idx & 31;
        size_t go = (size_t)(brow + r) * HDIM + j0 + j;
        out_h[go] = shH[r * 33 + j];
        out_c[go] = shC[r * 33 + j];
    }
}

// ---------------------------------------------------------------- head
__global__ void head_kernel(const float* __restrict__ hbuf,
                            const float* __restrict__ Wout,
                            const float* __restrict__ bout,
                            float* __restrict__ pre_label)
{
    int warp = (blockIdx.x * blockDim.x + threadIdx.x) >> 5;
    int lane = threadIdx.x & 31;
    if (warp >= BSZ) return;
    const float* row = hbuf + (size_t)warp * HDIM;
    float s0 = 0.f, s1 = 0.f;
    #pragma unroll 4
    for (int j = lane; j < HDIM; j += 32) {
        float v = row[j];
        s0 += v * Wout[j * 2 + 0];
        s1 += v * Wout[j * 2 + 1];
    }
    #pragma unroll
    for (int off = 16; off; off >>= 1) {
        s0 += __shfl_xor_sync(0xffffffffu, s0, off);
        s1 += __shfl_xor_sync(0xffffffffu, s1, off);
    }
    if (lane == 0) {
        s0 += bout[0];
        s1 += bout[1];
        float mx = fmaxf(s0, s1);
        float e0 = __expf(s0 - mx), e1 = __expf(s1 - mx);
        float inv = 1.f / (e0 + e1);
        pre_label[warp * 2 + 0] = e0 * inv;
        pre_label[warp * 2 + 1] = e1 * inv;
    }
}

// ---------------------------------------------------------------- launch
extern "C" void kernel_launch(void* const* d_in, const int* in_sizes, int n_in,
                              void* d_out, int out_size)
{
    const float* x    = (const float*)d_in[0];
    const float* h    = (const float*)d_in[1];
    const float* c    = (const float*)d_in[2];
    const float* Uf   = (const float*)d_in[3];
    const float* Vf   = (const float*)d_in[4];
    const float* bf   = (const float*)d_in[5];
    const float* Ui   = (const float*)d_in[6];
    const float* Vi   = (const float*)d_in[7];
    const float* bi   = (const float*)d_in[8];
    const float* Uo   = (const float*)d_in[9];
    const float* Vo   = (const float*)d_in[10];
    const float* bo   = (const float*)d_in[11];
    const float* Uc   = (const float*)d_in[12];
    const float* Vc   = (const float*)d_in[13];
    const float* bc   = (const float*)d_in[14];
    const float* Wout = (const float*)d_in[15];
    const float* bout = (const float*)d_in[16];

    float* out       = (float*)d_out;
    float* pre_label = out;                       // [B,2]
    float* out_h     = out + (size_t)BSZ * 2;     // [B,512]
    float* out_c     = out_h + (size_t)BSZ * HDIM;

    cudaFuncSetAttribute(lstm_gemm, cudaFuncAttributeMaxDynamicSharedMemorySize, SMEM_TOTAL);

    pack_W<<<(KTOT * HDIM + 255) / 256, 256>>>(Uf, Vf, bf, Ui, Vi, bi,
                                               Uo, Vo, bo, Uc, Vc, bc);
    conv_A<<<(int)(((size_t)BSZ * (KTOT / 8) + 255) / 256), 256>>>(x, h);
    lstm_gemm<<<dim3(NPK / BN, BSZ / BM), NTHR, SMEM_TOTAL>>>(c, out_h, out_c);
    head_kernel<<<(BSZ * 32 + 255) / 256, 256>>>(out_h, Wout, bout, pre_label);
}

// round 17
// speedup vs baseline: 2.7548x; 1.3464x over previous
#include <cuda_runtime.h>
#include <cuda_fp16.h>
#include <cstdint>
#include <math.h>

// Problem constants
#define BSZ   32768
#define HDIM  512
#define KTOT  1024          // concat(x,h)
#define NPK   2048          // 4 gates * 512, interleaved (j,gate): col = 4*j+g

// GEMM tiling: 512 threads, 16 warps (4 per SMSP), warp tile 64x32
#define BM    256           // rows per CTA
#define BN    128           // packed cols per CTA (= 32 j's)
#define BK    64            // K per iteration
#define NCH   (KTOT / BK)   // 16 iterations
#define NST   3             // cp.async pipeline stages
#define NTHR  512

// A and B single fp16 (measured error 2.2e-4, gate 1e-3).
__device__ __half g_Apk[(size_t)BSZ * KTOT];   // 64 MB
__device__ __half g_Bpk[(size_t)NPK * KTOT];   // 4 MB
__device__ float  g_bp[NPK];

// ---------------------------------------------------------------- helpers
__device__ __forceinline__ uint32_t smem_u32(const void* p) {
    uint32_t a;
    asm("{ .reg .u64 t; cvta.to.shared.u64 t, %1; cvt.u32.u64 %0, t; }" : "=r"(a) : "l"(p));
    return a;
}
__device__ __forceinline__ uint32_t swz(uint32_t off) {   // xor swizzle on 128B rows
    return off ^ ((off >> 3) & 0x70);
}
__device__ __forceinline__ void cpa16(uint32_t dst, const void* src) {
    asm volatile("cp.async.cg.shared.global [%0], [%1], 16;" :: "r"(dst), "l"(src) : "memory");
}
__device__ __forceinline__ void cpa_commit() { asm volatile("cp.async.commit_group;" ::: "memory"); }
__device__ __forceinline__ void cpa_wait1()  { asm volatile("cp.async.wait_group 1;" ::: "memory"); }
__device__ __forceinline__ void cpa_wait0()  { asm volatile("cp.async.wait_group 0;" ::: "memory"); }

__device__ __forceinline__ void ldsm4(uint32_t* r, uint32_t addr) {
    asm volatile("ldmatrix.sync.aligned.m8n8.x4.shared.b16 {%0,%1,%2,%3}, [%4];"
        : "=r"(r[0]), "=r"(r[1]), "=r"(r[2]), "=r"(r[3]) : "r"(addr));
}
__device__ __forceinline__ void mma16816(float* d, const uint32_t* a, const uint32_t* b) {
    asm volatile(
        "mma.sync.aligned.m16n8k16.row.col.f32.f16.f16.f32 "
        "{%0,%1,%2,%3}, {%4,%5,%6,%7}, {%8,%9}, {%0,%1,%2,%3};"
        : "+f"(d[0]), "+f"(d[1]), "+f"(d[2]), "+f"(d[3])
        : "r"(a[0]), "r"(a[1]), "r"(a[2]), "r"(a[3]), "r"(b[0]), "r"(b[1]));
}

// Fast gate nonlinearities (error ~1e-6, far under the 2.2e-4 fp16 floor)
__device__ __forceinline__ float fast_sigmoid(float x) {
    return __fdividef(1.f, 1.f + __expf(-x));
}
__device__ __forceinline__ float fast_tanh(float x) {
    float t = __expf(-2.f * fabsf(x));
    float r = __fdividef(1.f - t, 1.f + t);
    return copysignf(r, x);
}

// ---------------------------------------------------------------- fused prep
// Blocks [0, A_BLOCKS): convert concat(x,h) rows to fp16 (8 k's per thread).
// Blocks [A_BLOCKS, A_BLOCKS+W_BLOCKS): pack weights to fp16 gate-interleaved.
#define A_BLOCKS ((BSZ * (KTOT / 8)) / 256)   // 16384
#define W_BLOCKS ((KTOT * HDIM) / 256)        // 2048

__global__ void prep(
    const float* __restrict__ x, const float* __restrict__ h,
    const float* __restrict__ Uf, const float* __restrict__ Vf, const float* __restrict__ bf,
    const float* __restrict__ Ui, const float* __restrict__ Vi, const float* __restrict__ bi,
    const float* __restrict__ Uo, const float* __restrict__ Vo, const float* __restrict__ bo,
    const float* __restrict__ Uc, const float* __restrict__ Vc, const float* __restrict__ bc)
{
    if (blockIdx.x < A_BLOCKS) {
        size_t t = (size_t)blockIdx.x * 256 + threadIdx.x;
        int row = (int)(t >> 7);
        int kg  = ((int)t & 127) * 8;
        const float* src = (kg < HDIM) ? (x + (size_t)row * HDIM + kg)
                                       : (h + (size_t)row * HDIM + (kg - HDIM));
        float4 v0 = *(const float4*)(src);
        float4 v1 = *(const float4*)(src + 4);
        float v[8] = {v0.x, v0.y, v0.z, v0.w, v1.x, v1.y, v1.z, v1.w};
        __half o[8];
        #pragma unroll
        for (int e = 0; e < 8; e++) o[e] = __float2half(v[e]);
        *(uint4*)&g_Apk[(size_t)row * KTOT + kg] = *(uint4*)o;
    } else {
        int idx = (blockIdx.x - A_BLOCKS) * 256 + threadIdx.x;   // over KTOT*HDIM
        int j = idx & (HDIM - 1);
        int k = idx >> 9;
        const float* Us[4] = {Uf, Ui, Uo, Uc};
        const float* Vs[4] = {Vf, Vi, Vo, Vc};
        const float* bs[4] = {bf, bi, bo, bc};
        #pragma unroll
        for (int g = 0; g < 4; g++) {
            float v = (k < HDIM) ? Us[g][(size_t)k * HDIM + j]
                                 : Vs[g][(size_t)(k - HDIM) * HDIM + j];
            size_t n = (size_t)(4 * j + g);
            g_Bpk[n * KTOT + k] = __float2half(v);
            if (k == 0) g_bp[4 * j + g] = bs[g][j];
        }
    }
}

// ---------------------------------------------------------------- main GEMM
// SMEM: 3 stages x 48KB (A 32KB | B 16KB), then shC (256x36 f32), shH (256x36)
#define STAGE_BYTES 49152
#define SMEM_C_OFF  (NST * STAGE_BYTES)            // 147456
#define CH_PITCH    36                              // floats per row (16B-aligned, bank-safe)
#define CH_BYTES    (256 * CH_PITCH * 4)            // 36864
#define SMEM_H_OFF  (SMEM_C_OFF + CH_BYTES)
#define SMEM_TOTAL  (SMEM_H_OFF + CH_BYTES)         // 221184 (216KB)

__device__ __forceinline__ void load_chunk(uint32_t st,
                                           const __half* Asrc,
                                           const __half* Bsrc,
                                           int c, int tid)
{
    const char* ap = (const char*)Asrc;
    const char* bp = (const char*)Bsrc;
    #pragma unroll
    for (int kq = 0; kq < 4; kq++) {       // A: 2048 16B-units
        int q = tid + NTHR * kq;
        int r = q >> 3, u = q & 7;
        uint32_t soff = swz((uint32_t)(r << 7) + (uint32_t)(u << 4));
        size_t go = ((size_t)r << 11) + ((size_t)c << 7) + ((size_t)u << 4);
        cpa16(st + soff, ap + go);
    }
    #pragma unroll
    for (int kq = 0; kq < 2; kq++) {       // B: 1024 16B-units
        int q = tid + NTHR * kq;
        int r = q >> 3, u = q & 7;
        uint32_t soff = swz((uint32_t)(r << 7) + (uint32_t)(u << 4));
        size_t go = ((size_t)r << 11) + ((size_t)c << 7) + ((size_t)u << 4);
        cpa16(st + 32768 + soff, bp + go);
    }
}

__global__ void __launch_bounds__(NTHR, 1) lstm_gemm(
    const float* __restrict__ c_in,
    float* __restrict__ out_h, float* __restrict__ out_c)
{
    extern __shared__ char smem[];
    uint32_t sb = smem_u32(smem);
    const int tid  = threadIdx.x;
    const int lane = tid & 31;
    const int wid  = tid >> 5;
    const int wm   = wid & 3;      // 4 warp-rows of 64
    const int wn   = wid >> 2;     // 4 warp-cols of 32
    const int brow = blockIdx.y * BM;
    const int bcol = blockIdx.x * BN;
    const int j0   = bcol >> 2;    // 32 j's per CTA

    const __half* Asrc = g_Apk + (size_t)brow * KTOT;
    const __half* Bsrc = g_Bpk + (size_t)bcol * KTOT;

    float acc[4][4][4];
    #pragma unroll
    for (int mt = 0; mt < 4; mt++)
        #pragma unroll
        for (int nt = 0; nt < 4; nt++)
            #pragma unroll
            for (int e = 0; e < 4; e++) acc[mt][nt][e] = 0.f;

    // prologue: fill 2 stages
    load_chunk(sb + 0 * STAGE_BYTES, Asrc, Bsrc, 0, tid); cpa_commit();
    load_chunk(sb + 1 * STAGE_BYTES, Asrc, Bsrc, 1, tid); cpa_commit();

    // ldmatrix address components
    const int a_row = wm * 64 + (lane & 15);              // + mt*16
    const int a_kb  = (lane >> 4) * 16;                   // + g*32
    const int b_row = (lane & 7) + ((lane >> 4) & 1) * 8; // + wn*32 + ntp*16
    const int b_kb  = ((lane >> 3) & 1) * 16;             // + g*32

    for (int i = 0; i < NCH; i++) {
        if (i == NCH - 1) cpa_wait0(); else cpa_wait1();
        __syncthreads();

        if (i + 2 < NCH) {
            load_chunk(sb + ((i + 2) % 3) * STAGE_BYTES, Asrc, Bsrc, i + 2, tid);
            cpa_commit();
        } else if (i == NCH - 2) {
            // prefetch c tile into shC as its own cp.async group
            const char* cp = (const char*)(c_in + (size_t)brow * HDIM + j0);
            #pragma unroll
            for (int kq = 0; kq < 4; kq++) {
                int q = tid + NTHR * kq;          // 0..2047: 256 rows x 8 16B-units
                int r = q >> 3, u = q & 7;
                cpa16(sb + SMEM_C_OFF + (uint32_t)(r * (CH_PITCH * 4) + u * 16),
                      cp + (size_t)r * (HDIM * 4) + (size_t)u * 16);
            }
            cpa_commit();
        }

        uint32_t st = sb + (i % 3) * STAGE_BYTES;

        #pragma unroll
        for (int g = 0; g < 4; g++) {                     // 4 k16 groups in BK=64
            uint32_t kk = (uint32_t)(g * 32);
            uint32_t ah[4][4], bh[4][2];
            #pragma unroll
            for (int mt = 0; mt < 4; mt++) {
                uint32_t roff = (uint32_t)((a_row + mt * 16) << 7);
                ldsm4(ah[mt], st + swz(roff + (uint32_t)a_kb + kk));
            }
            #pragma unroll
            for (int ntp = 0; ntp < 2; ntp++) {
                uint32_t roff = (uint32_t)((wn * 32 + ntp * 16 + b_row) << 7);
                uint32_t t4[4];
                ldsm4(t4, st + 32768 + swz(roff + (uint32_t)b_kb + kk));
                bh[2 * ntp][0] = t4[0]; bh[2 * ntp][1] = t4[1];
                bh[2 * ntp + 1][0] = t4[2]; bh[2 * ntp + 1][1] = t4[3];
            }
            #pragma unroll
            for (int mt = 0; mt < 4; mt++)
                #pragma unroll
                for (int nt = 0; nt < 4; nt++)
                    mma16816(acc[mt][nt], ah[mt], bh[nt]);
        }
    }

    // -------- epilogue: c already in shC (cp.async), gates, h/c via SMEM
    __syncthreads();
    float* shC = (float*)(smem + SMEM_C_OFF);   // [256][36]
    float* shH = (float*)(smem + SMEM_H_OFF);   // [256][36]

    #pragma unroll
    for (int mt = 0; mt < 4; mt++) {
        #pragma unroll
        for (int nt = 0; nt < 4; nt++) {
            int nb = wn * 32 + nt * 8 + 2 * (lane & 3);   // local packed col (pair base)
            float bA = __ldg(&g_bp[bcol + nb]);
            float bB = __ldg(&g_bp[bcol + nb + 1]);
            #pragma unroll
            for (int hf = 0; hf < 2; hf++) {
                int row = wm * 64 + mt * 16 + (lane >> 2) + hf * 8;
                float p0 = acc[mt][nt][2 * hf + 0] + bA;
                float p1 = acc[mt][nt][2 * hf + 1] + bB;
                float q0 = __shfl_xor_sync(0xffffffffu, p0, 1);
                float q1 = __shfl_xor_sync(0xffffffffu, p1, 1);
                if ((lane & 1) == 0) {
                    // even lane holds (f,i); partner lane holds (o,c)
                    float fg = fast_sigmoid(p0);
                    float ig = fast_sigmoid(p1);
                    float og = fast_sigmoid(q0);
                    float ch = fast_tanh(q1);
                    int jl = nb >> 2;
                    float co = shC[row * CH_PITCH + jl];
                    float cn = fg * co + ig * ch;
                    float hn = og * fast_tanh(cn);
                    shC[row * CH_PITCH + jl] = cn;
                    shH[row * CH_PITCH + jl] = hn;
                }
            }
        }
    }
    __syncthreads();

    for (int idx = tid; idx < 256 * 32; idx += NTHR) {
        int r = idx >> 5, j = idx & 31;
        size_t go = (size_t)(brow + r) * HDIM + j0 + j;
        out_h[go] = shH[r * CH_PITCH + j];
        out_c[go] = shC[r * CH_PITCH + j];
    }
}

// ---------------------------------------------------------------- head
__global__ void head_kernel(const float* __restrict__ hbuf,
                            const float* __restrict__ Wout,
                            const float* __restrict__ bout,
                            float* __restrict__ pre_label)
{
    int warp = (blockIdx.x * blockDim.x + threadIdx.x) >> 5;
    int lane = threadIdx.x & 31;
    if (warp >= BSZ) return;
    const float* row = hbuf + (size_t)warp * HDIM;
    float s0 = 0.f, s1 = 0.f;
    #pragma unroll
    for (int j = lane * 4; j < HDIM; j += 128) {
        float4 hv  = *(const float4*)(row + j);
        float4 w01 = *(const float4*)(Wout + 2 * j);       // pairs (j), (j+1)
        float4 w23 = *(const float4*)(Wout + 2 * j + 4);   // pairs (j+2), (j+3)
        s0 += hv.x * w01.x + hv.y * w01.z + hv.z * w23.x + hv.w * w23.z;
        s1 += hv.x * w01.y + hv.y * w01.w + hv.z * w23.y + hv.w * w23.w;
    }
    #pragma unroll
    for (int off = 16; off; off >>= 1) {
        s0 += __shfl_xor_sync(0xffffffffu, s0, off);
        s1 += __shfl_xor_sync(0xffffffffu, s1, off);
    }
    if (lane == 0) {
        s0 += bout[0];
        s1 += bout[1];
        float mx = fmaxf(s0, s1);
        float e0 = __expf(s0 - mx), e1 = __expf(s1 - mx);
        float inv = __fdividef(1.f, e0 + e1);
        pre_label[warp * 2 + 0] = e0 * inv;
        pre_label[warp * 2 + 1] = e1 * inv;
    }
}

// ---------------------------------------------------------------- launch
extern "C" void kernel_launch(void* const* d_in, const int* in_sizes, int n_in,
                              void* d_out, int out_size)
{
    const float* x    = (const float*)d_in[0];
    const float* h    = (const float*)d_in[1];
    const float* c    = (const float*)d_in[2];
    const float* Uf   = (const float*)d_in[3];
    const float* Vf   = (const float*)d_in[4];
    const float* bf   = (const float*)d_in[5];
    const float* Ui   = (const float*)d_in[6];
    const float* Vi   = (const float*)d_in[7];
    const float* bi   = (const float*)d_in[8];
    const float* Uo   = (const float*)d_in[9];
    const float* Vo   = (const float*)d_in[10];
    const float* bo   = (const float*)d_in[11];
    const float* Uc   = (const float*)d_in[12];
    const float* Vc   = (const float*)d_in[13];
    const float* bc   = (const float*)d_in[14];
    const float* Wout = (const float*)d_in[15];
    const float* bout = (const float*)d_in[16];

    float* out       = (float*)d_out;
    float* pre_label = out;                       // [B,2]
    float* out_h     = out + (size_t)BSZ * 2;     // [B,512]
    float* out_c     = out_h + (size_t)BSZ * HDIM;

    cudaFuncSetAttribute(lstm_gemm, cudaFuncAttributeMaxDynamicSharedMemorySize, SMEM_TOTAL);

    prep<<<A_BLOCKS + W_BLOCKS, 256>>>(x, h, Uf, Vf, bf, Ui, Vi, bi,
                                       Uo, Vo, bo, Uc, Vc, bc);
    lstm_gemm<<<dim3(NPK / BN, BSZ / BM), NTHR, SMEM_TOTAL>>>(c, out_h, out_c);
    head_kernel<<<(BSZ * 32 + 255) / 256, 256>>>(out_h, Wout, bout, pre_label);
}